// round 12
// baseline (speedup 1.0000x reference)
#include <cuda_runtime.h>
#include <math.h>

#define B_     64
#define N_     8400
#define M_     64
#define TPB    256
#define P_     4                        // preds per thread
#define STRIP  (TPB * P_)               // 1024 preds per block
#define NCHUNK 9                        // ceil(8400 / 1024)
#define TOTAL_BLOCKS (B_ * NCHUNK)

// Deterministic scratch (no allocation). Zero-init by CUDA runtime.
__device__ float g_pconf[B_ * NCHUNK];
__device__ float g_pciou[B_ * NCHUNK];
__device__ float g_pnpos[B_ * NCHUNK];
__device__ unsigned int g_count;

__device__ __forceinline__ float focal_term(float l, bool matched)
{
    const float t = matched ? 1.0f : 0.0f;
    const float bce = fmaxf(l, 0.0f) - l * t + __logf(1.0f + __expf(-fabsf(l)));
    const float pt  = __expf(-bce);
    const float om  = 1.0f - pt;
    return 0.25f * om * om * bce;       // ALPHA=0.25, GAMMA=2
}

__device__ __forceinline__ float ciou_term(float x1, float y1, float x2, float y2,
                                           float4 g)
{
    const float xi1 = fmaxf(x1, g.x), yi1 = fmaxf(y1, g.y);
    const float xi2 = fminf(x2, g.z), yi2 = fminf(y2, g.w);
    const float inter = fmaxf(xi2 - xi1, 0.0f) * fmaxf(yi2 - yi1, 0.0f);
    const float uni = (x2 - x1) * (y2 - y1) + (g.z - g.x) * (g.w - g.y) - inter;
    const float iou = __fdividef(inter, uni + 1e-7f);

    const float xc1 = fminf(x1, g.x), yc1 = fminf(y1, g.y);
    const float xc2 = fmaxf(x2, g.z), yc2 = fmaxf(y2, g.w);
    const float dw = xc2 - xc1, dh = yc2 - yc1;
    const float diag = dw * dw + dh * dh + 1e-7f;
    const float ddx = (g.x + g.z) * 0.5f - (x1 + x2) * 0.5f;
    const float ddy = (g.y + g.w) * 0.5f - (y1 + y2) * 0.5f;
    const float dist = ddx * ddx + ddy * ddy;
    const float diou = 1.0f - iou + __fdividef(dist, diag);

    const float wp = x2 - x1, hp = y2 - y1;
    const float wg = g.z - g.x, hg = g.w - g.y;
    const float c4pi2 = 4.0f / (float)(M_PI * M_PI);
    const float dat = atanf(__fdividef(wg, hg)) - atanf(__fdividef(wp, hp));
    const float v = c4pi2 * dat * dat;
    const float alpha = __fdividef(v, 1.0f - iou + v + 1e-7f);
    return diou + alpha * v;
}

__global__ __launch_bounds__(TPB, 3)
void loss_fused(const float* __restrict__ preds, const float* __restrict__ targets,
                float* __restrict__ out)
{
    __shared__ float4 sbox[M_];
    __shared__ float  sarea[M_];

    const int b   = blockIdx.y;
    const int tid = threadIdx.x;

    if (tid < M_) {
        const float* t = targets + ((size_t)b * M_ + tid) * 4;
        const float cx = t[0], cy = t[1], w = t[2], h = t[3];
        const float x1 = cx - 0.5f * w, y1 = cy - 0.5f * h;
        const float x2 = cx + 0.5f * w, y2 = cy + 0.5f * h;
        sbox[tid]  = make_float4(x1, y1, x2, y2);
        sarea[tid] = (x2 - x1) * (y2 - y1);
    }
    __syncthreads();

    bool  valid[P_];
    float px1[P_], py1[P_], px2[P_], py2[P_], parea[P_], plog[P_];

    #pragma unroll
    for (int k = 0; k < P_; k++) {
        const int n = blockIdx.x * STRIP + k * TPB + tid;
        valid[k] = (n < N_);
        const float* p = preds + ((size_t)b * N_ + (valid[k] ? n : 0)) * 5;
        const float cx = p[0], cy = p[1], w = p[2], h = p[3];
        plog[k] = p[4];
        px1[k] = cx - 0.5f * w;  py1[k] = cy - 0.5f * h;
        px2[k] = cx + 0.5f * w;  py2[k] = cy + 0.5f * h;
        parea[k] = (px2[k] - px1[k]) * (py2[k] - py1[k]);
    }

    // Division-free IoU argmax. iou monotone in inter/S with S = areaP + areaT.
    // Updates as ternary selects (pred-as-data FSEL). The shared-memory tile
    // for iteration m+1 is prefetched into registers while tile m computes,
    // hiding the ~29-cycle LDS latency (the 64-reg cap previously blocked
    // ptxas from doing this; launch_bounds(256,3) grants 85 regs).
    float bI[P_], bS[P_];
    int   bIdx[P_];
    #pragma unroll
    for (int k = 0; k < P_; k++) { bI[k] = -1.0f; bS[k] = 1.0f; bIdx[k] = 0; }

    float4 tb = sbox[0];
    float  ar = sarea[0];

    #pragma unroll 8
    for (int m = 0; m < M_; m++) {
        const float4 tbc = tb;
        const float  arc = ar;
        const int mn = (m + 1 < M_) ? (m + 1) : (M_ - 1);
        tb = sbox[mn];          // prefetch next tile (overlaps compute below)
        ar = sarea[mn];
        #pragma unroll
        for (int k = 0; k < P_; k++) {
            const float dx = fminf(px2[k], tbc.z) - fmaxf(px1[k], tbc.x);
            const float dy = fminf(py2[k], tbc.w) - fmaxf(py1[k], tbc.y);
            // relu only on dx: dy<0 yields a fake-negative inter which can only
            // win when nothing overlaps (then matched=false and bIdx is unused).
            const float inter = fmaxf(dx, 0.0f) * dy;
            const float S     = parea[k] + arc;
            // inter/S > bI/bS  <=>  inter*bS - bI*S > 0   (S,bS > 0)
            const bool  upd = fmaf(inter, bS[k], -bI[k] * S) > 0.0f;
            bI[k]   = upd ? inter : bI[k];
            bS[k]   = upd ? S     : bS[k];
            bIdx[k] = upd ? m     : bIdx[k];
        }
    }

    float conf_c = 0.0f, ciou_c = 0.0f, pos_c = 0.0f;
    #pragma unroll
    for (int k = 0; k < P_; k++) {
        const bool matched = valid[k] && (bI[k] > 0.3f * (bS[k] - bI[k]));
        if (valid[k]) conf_c += focal_term(plog[k], matched);
        if (matched) {
            ciou_c += ciou_term(px1[k], py1[k], px2[k], py2[k], sbox[bIdx[k]]);
            pos_c  += 1.0f;
        }
    }

    // Deterministic block reduction
    const unsigned msk = 0xffffffffu;
    #pragma unroll
    for (int off = 16; off; off >>= 1) {
        conf_c += __shfl_down_sync(msk, conf_c, off);
        ciou_c += __shfl_down_sync(msk, ciou_c, off);
        pos_c  += __shfl_down_sync(msk, pos_c,  off);
    }
    __shared__ float red[3][TPB / 32];
    const int wid = tid >> 5, lid = tid & 31;
    if (lid == 0) { red[0][wid] = conf_c; red[1][wid] = ciou_c; red[2][wid] = pos_c; }
    __syncthreads();

    __shared__ int s_last;
    if (tid == 0) {
        float c = 0.0f, d = 0.0f, e = 0.0f;
        #pragma unroll
        for (int i = 0; i < TPB / 32; i++) { c += red[0][i]; d += red[1][i]; e += red[2][i]; }
        const int idx = b * NCHUNK + blockIdx.x;
        g_pconf[idx] = c; g_pciou[idx] = d; g_pnpos[idx] = e;
        __threadfence();
        const unsigned v = atomicAdd(&g_count, 1u);
        s_last = (v == TOTAL_BLOCKS - 1) ? 1 : 0;
    }
    __syncthreads();

    // Last block performs the deterministic finalization
    if (s_last) {
        __shared__ float sc[B_], sbx[B_], sn[B_];
        if (tid < B_) {
            float c = 0.0f, d = 0.0f, e = 0.0f;
            #pragma unroll
            for (int i = 0; i < NCHUNK; i++) {
                const int idx = tid * NCHUNK + i;
                c += g_pconf[idx]; d += g_pciou[idx]; e += g_pnpos[idx];
            }
            sc[tid]  = c;
            sbx[tid] = (e > 0.0f) ? (d / e) : 0.0f;
            sn[tid]  = (e > 0.0f) ? 1.0f : 0.0f;
        }
        __syncthreads();
        if (tid == 0) {
            float C = 0.0f, Bx = 0.0f, Ni = 0.0f;
            #pragma unroll
            for (int i = 0; i < B_; i++) { C += sc[i]; Bx += sbx[i]; Ni += sn[i]; }
            const float conf_loss = C / (float)(B_ * N_);
            const float box_loss  = Bx / fmaxf(Ni, 1.0f);
            out[0] = conf_loss + 7.5f * box_loss;
            g_count = 0;   // reset for next graph replay
        }
    }
}

extern "C" void kernel_launch(void* const* d_in, const int* in_sizes, int n_in,
                              void* d_out, int out_size)
{
    const float* preds   = (const float*)d_in[0];
    const float* targets = (const float*)d_in[1];
    if (n_in >= 2 && in_sizes[0] == B_ * M_ * 4 && in_sizes[1] == B_ * N_ * 5) {
        preds   = (const float*)d_in[1];
        targets = (const float*)d_in[0];
    }
    float* out = (float*)d_out;

    dim3 grid(NCHUNK, B_);
    loss_fused<<<grid, TPB>>>(preds, targets, out);
}

// round 13
// speedup vs baseline: 1.0332x; 1.0332x over previous
#include <cuda_runtime.h>
#include <math.h>

#define B_     64
#define N_     8400
#define M_     64
#define TPB    256
#define P_     3                        // preds per thread
#define STRIP  (TPB * P_)               // 768 preds per block
#define NCHUNK 11                       // ceil(8400 / 768) -> 8448, 0.57% waste
#define TOTAL_BLOCKS (B_ * NCHUNK)

// Deterministic scratch (no allocation). Zero-init by CUDA runtime.
__device__ float g_pconf[B_ * NCHUNK];
__device__ float g_pciou[B_ * NCHUNK];
__device__ float g_pnpos[B_ * NCHUNK];
__device__ unsigned int g_count;

__device__ __forceinline__ float focal_term(float l, bool matched)
{
    const float t = matched ? 1.0f : 0.0f;
    const float bce = fmaxf(l, 0.0f) - l * t + __logf(1.0f + __expf(-fabsf(l)));
    const float pt  = __expf(-bce);
    const float om  = 1.0f - pt;
    return 0.25f * om * om * bce;       // ALPHA=0.25, GAMMA=2
}

__device__ __forceinline__ float ciou_term(float x1, float y1, float x2, float y2,
                                           float4 g)
{
    const float xi1 = fmaxf(x1, g.x), yi1 = fmaxf(y1, g.y);
    const float xi2 = fminf(x2, g.z), yi2 = fminf(y2, g.w);
    const float inter = fmaxf(xi2 - xi1, 0.0f) * fmaxf(yi2 - yi1, 0.0f);
    const float uni = (x2 - x1) * (y2 - y1) + (g.z - g.x) * (g.w - g.y) - inter;
    const float iou = __fdividef(inter, uni + 1e-7f);

    const float xc1 = fminf(x1, g.x), yc1 = fminf(y1, g.y);
    const float xc2 = fmaxf(x2, g.z), yc2 = fmaxf(y2, g.w);
    const float dw = xc2 - xc1, dh = yc2 - yc1;
    const float diag = dw * dw + dh * dh + 1e-7f;
    const float ddx = (g.x + g.z) * 0.5f - (x1 + x2) * 0.5f;
    const float ddy = (g.y + g.w) * 0.5f - (y1 + y2) * 0.5f;
    const float dist = ddx * ddx + ddy * ddy;
    const float diou = 1.0f - iou + __fdividef(dist, diag);

    const float wp = x2 - x1, hp = y2 - y1;
    const float wg = g.z - g.x, hg = g.w - g.y;
    const float c4pi2 = 4.0f / (float)(M_PI * M_PI);
    const float dat = atanf(__fdividef(wg, hg)) - atanf(__fdividef(wp, hp));
    const float v = c4pi2 * dat * dat;
    const float alpha = __fdividef(v, 1.0f - iou + v + 1e-7f);
    return diou + alpha * v;
}

__global__ __launch_bounds__(TPB, 5)
void loss_fused(const float* __restrict__ preds, const float* __restrict__ targets,
                float* __restrict__ out)
{
    __shared__ float4 sbox[M_];
    __shared__ float  sarea[M_];

    const int b   = blockIdx.y;
    const int tid = threadIdx.x;

    if (tid < M_) {
        const float* t = targets + ((size_t)b * M_ + tid) * 4;
        const float cx = t[0], cy = t[1], w = t[2], h = t[3];
        const float x1 = cx - 0.5f * w, y1 = cy - 0.5f * h;
        const float x2 = cx + 0.5f * w, y2 = cy + 0.5f * h;
        sbox[tid]  = make_float4(x1, y1, x2, y2);
        sarea[tid] = (x2 - x1) * (y2 - y1);
    }
    __syncthreads();

    bool  valid[P_];
    float px1[P_], py1[P_], px2[P_], py2[P_], parea[P_], plog[P_];

    #pragma unroll
    for (int k = 0; k < P_; k++) {
        const int n = blockIdx.x * STRIP + k * TPB + tid;
        valid[k] = (n < N_);
        const float* p = preds + ((size_t)b * N_ + (valid[k] ? n : 0)) * 5;
        const float cx = p[0], cy = p[1], w = p[2], h = p[3];
        plog[k] = p[4];
        px1[k] = cx - 0.5f * w;  py1[k] = cy - 0.5f * h;
        px2[k] = cx + 0.5f * w;  py2[k] = cy + 0.5f * h;
        parea[k] = (px2[k] - px1[k]) * (py2[k] - py1[k]);
    }

    // Division-free IoU argmax. iou monotone in inter/S with S = areaP + areaT.
    // Updates as ternary selects (pred-as-data FSEL). Exact reference rounding.
    float bI[P_], bS[P_];
    int   bIdx[P_];
    #pragma unroll
    for (int k = 0; k < P_; k++) { bI[k] = -1.0f; bS[k] = 1.0f; bIdx[k] = 0; }

    #pragma unroll 8
    for (int m = 0; m < M_; m++) {
        const float4 tb = sbox[m];
        const float  ar = sarea[m];
        #pragma unroll
        for (int k = 0; k < P_; k++) {
            const float dx = fminf(px2[k], tb.z) - fmaxf(px1[k], tb.x);
            const float dy = fminf(py2[k], tb.w) - fmaxf(py1[k], tb.y);
            // relu only on dx: dy<0 yields a fake-negative inter which can only
            // win when nothing overlaps (then matched=false and bIdx is unused).
            const float inter = fmaxf(dx, 0.0f) * dy;
            const float S     = parea[k] + ar;
            // inter/S > bI/bS  <=>  inter*bS - bI*S > 0   (S,bS > 0)
            const bool  upd = fmaf(inter, bS[k], -bI[k] * S) > 0.0f;
            bI[k]   = upd ? inter : bI[k];
            bS[k]   = upd ? S     : bS[k];
            bIdx[k] = upd ? m     : bIdx[k];
        }
    }

    float conf_c = 0.0f, ciou_c = 0.0f, pos_c = 0.0f;
    #pragma unroll
    for (int k = 0; k < P_; k++) {
        const bool matched = valid[k] && (bI[k] > 0.3f * (bS[k] - bI[k]));
        if (valid[k]) conf_c += focal_term(plog[k], matched);
        if (matched) {
            ciou_c += ciou_term(px1[k], py1[k], px2[k], py2[k], sbox[bIdx[k]]);
            pos_c  += 1.0f;
        }
    }

    // Deterministic block reduction
    const unsigned msk = 0xffffffffu;
    #pragma unroll
    for (int off = 16; off; off >>= 1) {
        conf_c += __shfl_down_sync(msk, conf_c, off);
        ciou_c += __shfl_down_sync(msk, ciou_c, off);
        pos_c  += __shfl_down_sync(msk, pos_c,  off);
    }
    __shared__ float red[3][TPB / 32];
    const int wid = tid >> 5, lid = tid & 31;
    if (lid == 0) { red[0][wid] = conf_c; red[1][wid] = ciou_c; red[2][wid] = pos_c; }
    __syncthreads();

    __shared__ int s_last;
    if (tid == 0) {
        float c = 0.0f, d = 0.0f, e = 0.0f;
        #pragma unroll
        for (int i = 0; i < TPB / 32; i++) { c += red[0][i]; d += red[1][i]; e += red[2][i]; }
        const int idx = b * NCHUNK + blockIdx.x;
        g_pconf[idx] = c; g_pciou[idx] = d; g_pnpos[idx] = e;
        __threadfence();
        const unsigned v = atomicAdd(&g_count, 1u);
        s_last = (v == TOTAL_BLOCKS - 1) ? 1 : 0;
    }
    __syncthreads();

    // Last block performs the deterministic finalization
    if (s_last) {
        __shared__ float sc[B_], sbx[B_], sn[B_];
        if (tid < B_) {
            float c = 0.0f, d = 0.0f, e = 0.0f;
            #pragma unroll
            for (int i = 0; i < NCHUNK; i++) {
                const int idx = tid * NCHUNK + i;
                c += g_pconf[idx]; d += g_pciou[idx]; e += g_pnpos[idx];
            }
            sc[tid]  = c;
            sbx[tid] = (e > 0.0f) ? (d / e) : 0.0f;
            sn[tid]  = (e > 0.0f) ? 1.0f : 0.0f;
        }
        __syncthreads();
        if (tid == 0) {
            float C = 0.0f, Bx = 0.0f, Ni = 0.0f;
            #pragma unroll
            for (int i = 0; i < B_; i++) { C += sc[i]; Bx += sbx[i]; Ni += sn[i]; }
            const float conf_loss = C / (float)(B_ * N_);
            const float box_loss  = Bx / fmaxf(Ni, 1.0f);
            out[0] = conf_loss + 7.5f * box_loss;
            g_count = 0;   // reset for next graph replay
        }
    }
}

extern "C" void kernel_launch(void* const* d_in, const int* in_sizes, int n_in,
                              void* d_out, int out_size)
{
    const float* preds   = (const float*)d_in[0];
    const float* targets = (const float*)d_in[1];
    if (n_in >= 2 && in_sizes[0] == B_ * M_ * 4 && in_sizes[1] == B_ * N_ * 5) {
        preds   = (const float*)d_in[1];
        targets = (const float*)d_in[0];
    }
    float* out = (float*)d_out;

    dim3 grid(NCHUNK, B_);
    loss_fused<<<grid, TPB>>>(preds, targets, out);
}

// round 14
// speedup vs baseline: 1.0532x; 1.0193x over previous
#include <cuda_runtime.h>
#include <math.h>

#define B_     64
#define N_     8400
#define M_     64
#define TPB    256
#define P_     3                        // preds per thread
#define STRIP  (TPB * P_)               // 768 preds per block
#define NCHUNK 11                       // ceil(8400 / 768) -> 8448, 0.57% waste
#define TOTAL_BLOCKS (B_ * NCHUNK)

// Deterministic scratch (no allocation). Zero-init by CUDA runtime.
__device__ float g_pconf[B_ * NCHUNK];
__device__ float g_pciou[B_ * NCHUNK];
__device__ float g_pnpos[B_ * NCHUNK];
__device__ unsigned int g_count;

__device__ __forceinline__ float focal_term(float l, bool matched)
{
    const float t = matched ? 1.0f : 0.0f;
    const float bce = fmaxf(l, 0.0f) - l * t + __logf(1.0f + __expf(-fabsf(l)));
    const float pt  = __expf(-bce);
    const float om  = 1.0f - pt;
    return 0.25f * om * om * bce;       // ALPHA=0.25, GAMMA=2
}

__device__ __forceinline__ float ciou_term(float x1, float y1, float x2, float y2,
                                           float4 g)
{
    const float xi1 = fmaxf(x1, g.x), yi1 = fmaxf(y1, g.y);
    const float xi2 = fminf(x2, g.z), yi2 = fminf(y2, g.w);
    const float inter = fmaxf(xi2 - xi1, 0.0f) * fmaxf(yi2 - yi1, 0.0f);
    const float uni = (x2 - x1) * (y2 - y1) + (g.z - g.x) * (g.w - g.y) - inter;
    const float iou = __fdividef(inter, uni + 1e-7f);

    const float xc1 = fminf(x1, g.x), yc1 = fminf(y1, g.y);
    const float xc2 = fmaxf(x2, g.z), yc2 = fmaxf(y2, g.w);
    const float dw = xc2 - xc1, dh = yc2 - yc1;
    const float diag = dw * dw + dh * dh + 1e-7f;
    const float ddx = (g.x + g.z) * 0.5f - (x1 + x2) * 0.5f;
    const float ddy = (g.y + g.w) * 0.5f - (y1 + y2) * 0.5f;
    const float dist = ddx * ddx + ddy * ddy;
    const float diou = 1.0f - iou + __fdividef(dist, diag);

    const float wp = x2 - x1, hp = y2 - y1;
    const float wg = g.z - g.x, hg = g.w - g.y;
    const float c4pi2 = 4.0f / (float)(M_PI * M_PI);
    const float dat = atanf(__fdividef(wg, hg)) - atanf(__fdividef(wp, hp));
    const float v = c4pi2 * dat * dat;
    const float alpha = __fdividef(v, 1.0f - iou + v + 1e-7f);
    return diou + alpha * v;
}

__global__ __launch_bounds__(TPB, 5)
void loss_fused(const float* __restrict__ preds, const float* __restrict__ targets,
                float* __restrict__ out)
{
    __shared__ float4 sbox[M_];
    __shared__ float  sarea[M_];

    const int b   = blockIdx.y;
    const int tid = threadIdx.x;

    if (tid < M_) {
        const float* t = targets + ((size_t)b * M_ + tid) * 4;
        const float cx = t[0], cy = t[1], w = t[2], h = t[3];
        const float x1 = cx - 0.5f * w, y1 = cy - 0.5f * h;
        const float x2 = cx + 0.5f * w, y2 = cy + 0.5f * h;
        sbox[tid]  = make_float4(x1, y1, x2, y2);
        sarea[tid] = (x2 - x1) * (y2 - y1);
    }
    __syncthreads();

    bool  valid[P_];
    float px1[P_], py1[P_], px2[P_], py2[P_], parea[P_], plog[P_];

    #pragma unroll
    for (int k = 0; k < P_; k++) {
        const int n = blockIdx.x * STRIP + k * TPB + tid;
        valid[k] = (n < N_);
        const float* p = preds + ((size_t)b * N_ + (valid[k] ? n : 0)) * 5;
        const float cx = p[0], cy = p[1], w = p[2], h = p[3];
        plog[k] = p[4];
        px1[k] = cx - 0.5f * w;  py1[k] = cy - 0.5f * h;
        px2[k] = cx + 0.5f * w;  py2[k] = cy + 0.5f * h;
        parea[k] = (px2[k] - px1[k]) * (py2[k] - py1[k]);
    }

    // Division-free IoU argmax. iou monotone in inter/S with S = areaP + areaT.
    // Compare: inter*bS > bI*S with the two products computed INDEPENDENTLY
    // (parallel FMULs) and a direct FSETP — loop-carried chain is
    // FSEL->FMUL->FSETP->FSEL (12 cyc) instead of FSEL->FMUL->FFMA->FSETP->FSEL.
    float bI[P_], bS[P_];
    int   bIdx[P_];
    #pragma unroll
    for (int k = 0; k < P_; k++) { bI[k] = -1.0f; bS[k] = 1.0f; bIdx[k] = 0; }

    #pragma unroll 16
    for (int m = 0; m < M_; m++) {
        const float4 tb = sbox[m];
        const float  ar = sarea[m];
        #pragma unroll
        for (int k = 0; k < P_; k++) {
            const float dx = fminf(px2[k], tb.z) - fmaxf(px1[k], tb.x);
            const float dy = fminf(py2[k], tb.w) - fmaxf(py1[k], tb.y);
            // relu only on dx: dy<0 yields a fake-negative inter which can only
            // win when nothing overlaps (then matched=false and bIdx is unused).
            const float inter = fmaxf(dx, 0.0f) * dy;
            const float S     = parea[k] + ar;
            const float lhs = inter * bS[k];
            const float rhs = bI[k] * S;
            const bool  upd = lhs > rhs;
            bI[k]   = upd ? inter : bI[k];
            bS[k]   = upd ? S     : bS[k];
            bIdx[k] = upd ? m     : bIdx[k];
        }
    }

    float conf_c = 0.0f, ciou_c = 0.0f, pos_c = 0.0f;
    #pragma unroll
    for (int k = 0; k < P_; k++) {
        const bool matched = valid[k] && (bI[k] > 0.3f * (bS[k] - bI[k]));
        if (valid[k]) conf_c += focal_term(plog[k], matched);
        if (matched) {
            ciou_c += ciou_term(px1[k], py1[k], px2[k], py2[k], sbox[bIdx[k]]);
            pos_c  += 1.0f;
        }
    }

    // Deterministic block reduction
    const unsigned msk = 0xffffffffu;
    #pragma unroll
    for (int off = 16; off; off >>= 1) {
        conf_c += __shfl_down_sync(msk, conf_c, off);
        ciou_c += __shfl_down_sync(msk, ciou_c, off);
        pos_c  += __shfl_down_sync(msk, pos_c,  off);
    }
    __shared__ float red[3][TPB / 32];
    const int wid = tid >> 5, lid = tid & 31;
    if (lid == 0) { red[0][wid] = conf_c; red[1][wid] = ciou_c; red[2][wid] = pos_c; }
    __syncthreads();

    __shared__ int s_last;
    if (tid == 0) {
        float c = 0.0f, d = 0.0f, e = 0.0f;
        #pragma unroll
        for (int i = 0; i < TPB / 32; i++) { c += red[0][i]; d += red[1][i]; e += red[2][i]; }
        const int idx = b * NCHUNK + blockIdx.x;
        g_pconf[idx] = c; g_pciou[idx] = d; g_pnpos[idx] = e;
        __threadfence();
        const unsigned v = atomicAdd(&g_count, 1u);
        s_last = (v == TOTAL_BLOCKS - 1) ? 1 : 0;
    }
    __syncthreads();

    // Last block performs the deterministic finalization
    if (s_last) {
        __shared__ float sc[B_], sbx[B_], sn[B_];
        if (tid < B_) {
            float c = 0.0f, d = 0.0f, e = 0.0f;
            #pragma unroll
            for (int i = 0; i < NCHUNK; i++) {
                const int idx = tid * NCHUNK + i;
                c += g_pconf[idx]; d += g_pciou[idx]; e += g_pnpos[idx];
            }
            sc[tid]  = c;
            sbx[tid] = (e > 0.0f) ? (d / e) : 0.0f;
            sn[tid]  = (e > 0.0f) ? 1.0f : 0.0f;
        }
        __syncthreads();
        if (tid == 0) {
            float C = 0.0f, Bx = 0.0f, Ni = 0.0f;
            #pragma unroll
            for (int i = 0; i < B_; i++) { C += sc[i]; Bx += sbx[i]; Ni += sn[i]; }
            const float conf_loss = C / (float)(B_ * N_);
            const float box_loss  = Bx / fmaxf(Ni, 1.0f);
            out[0] = conf_loss + 7.5f * box_loss;
            g_count = 0;   // reset for next graph replay
        }
    }
}

extern "C" void kernel_launch(void* const* d_in, const int* in_sizes, int n_in,
                              void* d_out, int out_size)
{
    const float* preds   = (const float*)d_in[0];
    const float* targets = (const float*)d_in[1];
    if (n_in >= 2 && in_sizes[0] == B_ * M_ * 4 && in_sizes[1] == B_ * N_ * 5) {
        preds   = (const float*)d_in[1];
        targets = (const float*)d_in[0];
    }
    float* out = (float*)d_out;

    dim3 grid(NCHUNK, B_);
    loss_fused<<<grid, TPB>>>(preds, targets, out);
}